// round 3
// baseline (speedup 1.0000x reference)
#include <cuda_runtime.h>
#include <math.h>

#define HH 64
#define WW 64
#define NUM_POS 48
#define CC 384
#define BB 32
#define SM_W 68           // padded smem row stride (floats): rows 16B-aligned
#define TILE_ROWS 66      // displaced rows [-1, 64]
#define TILE_COLS 66      // displaced cols [-1, 64]

struct __align__(16) PosParam {
    float wx0, wx1, wx2;
    float wy0, wy1, wy2;
    int   ox, oy;
};

__device__ PosParam g_pp[NUM_POS];

// ---- tiny LUT kernel: separable normalized Gaussian weights per position ----
__global__ void precompute_weights(const float* __restrict__ offset)
{
    const int p = threadIdx.x;
    if (p >= NUM_POS) return;
    const float offx = offset[p * 2 + 0];
    const float offy = offset[p * 2 + 1];
    const float rx = rintf(offx);                 // matches jnp.round (no .5 ties)
    const float ry = rintf(offy);
    const float fx = offx - rx;
    const float fy = offy - ry;

    // kern(ky,kx) = gy[ky]*gx[kx]; normalizer = (sum gx)(sum gy) -> fully separable
    float gx[3], gy[3], sx = 0.f, sy = 0.f;
    #pragma unroll
    for (int k = 0; k < 3; k++) {
        const float dx = (float)(k - 1) + fx;
        const float dy = (float)(k - 1) + fy;
        gx[k] = expf(-2.0f * dx * dx);            // sigma = 0.5
        gy[k] = expf(-2.0f * dy * dy);
        sx += gx[k];
        sy += gy[k];
    }
    const float ix = 1.0f / sx, iy = 1.0f / sy;
    PosParam pp;
    pp.wx0 = gx[0] * ix; pp.wx1 = gx[1] * ix; pp.wx2 = gx[2] * ix;
    pp.wy0 = gy[0] * iy; pp.wy1 = gy[1] * iy; pp.wy2 = gy[2] * iy;
    pp.ox = (int)rx;     pp.oy = (int)ry;
    g_pp[p] = pp;
}

// ---- main fused kernel: displace + separable 3x3 Gaussian ----
__global__ __launch_bounds__(256, 6)
void displace_gauss_kernel(const float* __restrict__ inp,
                           float* __restrict__ out)
{
    __shared__ float tile[TILE_ROWS * SM_W];

    const int c = blockIdx.x;          // channel 0..383
    const int b = blockIdx.y;          // batch 0..31
    const int pos = c >> 3;

    const PosParam pp = g_pp[pos];     // broadcast load, L1/const-cached
    const int ox = pp.ox, oy = pp.oy;

    // --- stage displaced + masked tile into smem (66x66 incl. conv halo) ---
    const float* __restrict__ src = inp + ((size_t)b * CC + c) * (HH * WW);
    for (int i = threadIdx.x; i < TILE_ROWS * TILE_COLS; i += 256) {
        const int yy = i / TILE_COLS - 1;   // displaced row in [-1, 64]
        const int xx = i % TILE_COLS - 1;   // displaced col in [-1, 64]
        const int sy = yy - oy;             // source row
        const int sx = xx - ox;             // source col
        float v = 0.0f;
        if ((unsigned)yy < HH && (unsigned)xx < WW &&
            (unsigned)sy < HH && (unsigned)sx < WW) {
            v = __ldg(&src[sy * WW + sx]);
        }
        tile[(yy + 1) * SM_W + (xx + 1)] = v;
    }
    __syncthreads();

    // --- separable conv: each thread does a 4-col x 4-row patch,
    //     rotating 3 horizontally-convolved rows through registers ---
    const int cg    = threadIdx.x & 15;     // column group (x4 = cg*4)
    const int strip = threadIdx.x >> 4;     // row strip (y0 = strip*4)
    const int x4 = cg << 2;
    const int y0 = strip << 2;

    const float wx0 = pp.wx0, wx1 = pp.wx1, wx2 = pp.wx2;
    const float wy0 = pp.wy0, wy1 = pp.wy1, wy2 = pp.wy2;

    // hconv of tile row t (t = displaced y + 1), producing 4 pixels x4..x4+3:
    // pixel x needs tile cols x .. x+2 (tile col = xx+1)
    #define HCONV(H, TROW)                                                     \
        {                                                                      \
            const float* _r = &tile[(TROW) * SM_W + x4];                       \
            const float4 va = *(const float4*)(_r);        /* cols x4..x4+3 */ \
            const float2 vb = *(const float2*)(_r + 4);    /* cols x4+4..5 */  \
            H.x = fmaf(wx2, va.z, fmaf(wx1, va.y, wx0 * va.x));                \
            H.y = fmaf(wx2, va.w, fmaf(wx1, va.z, wx0 * va.y));                \
            H.z = fmaf(wx2, vb.x, fmaf(wx1, va.w, wx0 * va.z));                \
            H.w = fmaf(wx2, vb.y, fmaf(wx1, vb.x, wx0 * va.w));                \
        }

    float* __restrict__ dst = out + ((size_t)b * CC + c) * (HH * WW);

    float4 h0, h1, hn;
    HCONV(h0, y0 + 0);                     // tile row for output y0-1
    HCONV(h1, y0 + 1);                     // tile row for output y0
    #pragma unroll
    for (int r = 0; r < 4; r++) {
        HCONV(hn, y0 + 2 + r);             // tile row for output y0+r+1
        float4 o;
        o.x = fmaf(wy2, hn.x, fmaf(wy1, h1.x, wy0 * h0.x));
        o.y = fmaf(wy2, hn.y, fmaf(wy1, h1.y, wy0 * h0.y));
        o.z = fmaf(wy2, hn.z, fmaf(wy1, h1.z, wy0 * h0.z));
        o.w = fmaf(wy2, hn.w, fmaf(wy1, h1.w, wy0 * h0.w));
        *(float4*)&dst[(y0 + r) * WW + x4] = o;
        h0 = h1;
        h1 = hn;
    }
    #undef HCONV
}

extern "C" void kernel_launch(void* const* d_in, const int* in_sizes, int n_in,
                              void* d_out, int out_size)
{
    const float* inp    = (const float*)d_in[0];   // (32, 384, 64, 64) fp32
    const float* offset = (const float*)d_in[1];   // (48, 2) fp32
    float* out          = (float*)d_out;           // (32, 384, 64, 64) fp32

    precompute_weights<<<1, 64>>>(offset);
    dim3 grid(CC, BB);   // one CTA per (b, c) plane
    displace_gauss_kernel<<<grid, 256>>>(inp, out);
}

// round 7
// speedup vs baseline: 1.5805x; 1.5805x over previous
#include <cuda_runtime.h>
#include <math.h>

#define HH 64
#define WW 64
#define NUM_POS 48
#define CC 384
#define BB 32
#define SM_W 68           // padded smem row stride (floats)

struct __align__(16) PosParam {
    float wx0, wx1, wx2;
    float wy0, wy1, wy2;
    int   ox, oy;
};

__device__ PosParam g_pp[NUM_POS];

// ---- tiny LUT kernel: separable normalized Gaussian weights per position ----
__global__ void precompute_weights(const float* __restrict__ offset)
{
    const int p = threadIdx.x;
    if (p >= NUM_POS) return;
    const float offx = offset[p * 2 + 0];
    const float offy = offset[p * 2 + 1];
    const float rx = rintf(offx);                 // == iw*16 exactly (jitter < 0.5)
    const float ry = rintf(offy);
    const float fx = offx - rx;
    const float fy = offy - ry;

    float gx[3], gy[3], sx = 0.f, sy = 0.f;
    #pragma unroll
    for (int k = 0; k < 3; k++) {
        const float dx = (float)(k - 1) + fx;
        const float dy = (float)(k - 1) + fy;
        gx[k] = expf(-2.0f * dx * dx);            // sigma = 0.5
        gy[k] = expf(-2.0f * dy * dy);
        sx += gx[k];
        sy += gy[k];
    }
    const float ix = 1.0f / sx, iy = 1.0f / sy;   // kern normalizer factors
    PosParam pp;
    pp.wx0 = gx[0] * ix; pp.wx1 = gx[1] * ix; pp.wx2 = gx[2] * ix;
    pp.wy0 = gy[0] * iy; pp.wy1 = gy[1] * iy; pp.wy2 = gy[2] * iy;
    pp.ox = (int)rx;     pp.oy = (int)ry;
    g_pp[p] = pp;
}

// ---- main fused kernel: displace + 3x3 Gaussian ----
__global__ __launch_bounds__(256, 8)
void displace_gauss_kernel(const float* __restrict__ inp,
                           float* __restrict__ out)
{
    __shared__ float tile[66 * SM_W];   // displaced plane + always-zero halo ring

    const int c = blockIdx.x;
    const int b = blockIdx.y;
    const int tid = threadIdx.x;

    const PosParam pp = g_pp[c >> 3];
    const int ox = pp.ox, oy = pp.oy;   // multiples of 16 by construction

    // full 3x3 weights (separable product), 9 regs
    float w[9];
    w[0] = pp.wy0 * pp.wx0; w[1] = pp.wy0 * pp.wx1; w[2] = pp.wy0 * pp.wx2;
    w[3] = pp.wy1 * pp.wx0; w[4] = pp.wy1 * pp.wx1; w[5] = pp.wy1 * pp.wx2;
    w[6] = pp.wy2 * pp.wx0; w[7] = pp.wy2 * pp.wx1; w[8] = pp.wy2 * pp.wx2;

    // --- zero halo ring (displaced coords -1 / 64 are always masked to 0) ---
    // 260 cells, 256 threads -> strided loop (tid 0..3 do two cells)
    for (int i = tid; i < 260; i += 256) {
        int r, cc;
        if (i < 66)       { r = 0;         cc = i;       }
        else if (i < 132) { r = 65;        cc = i - 66;  }
        else if (i < 196) { r = i - 131;   cc = 0;       }
        else              { r = i - 195;   cc = 65;      }
        tile[r * SM_W + cc] = 0.0f;
    }

    // --- interior fill: displaced (y,x) in [0,64)^2 -> tile[y+1][x+1] ---
    // ox multiple of 16 -> source float4 loads are 16B-aligned; whole float4
    // shares one validity predicate.
    const float* __restrict__ src = inp + ((size_t)b * CC + c) * (HH * WW);
    const int q     = tid & 15;         // column group
    const int x4    = q << 2;
    const int sx    = x4 - ox;
    const bool okx  = (unsigned)sx < (unsigned)WW;
    const int ybase = tid >> 4;

    #pragma unroll
    for (int k = 0; k < 4; k++) {
        const int y  = ybase + k * 16;
        const int sy = y - oy;
        float4 v = make_float4(0.f, 0.f, 0.f, 0.f);
        if (okx && (unsigned)sy < (unsigned)HH)
            v = *(const float4*)(src + sy * WW + sx);
        float* t = &tile[(y + 1) * SM_W + x4 + 1];
        t[0] = v.x; t[1] = v.y; t[2] = v.z; t[3] = v.w;
    }
    __syncthreads();

    // --- 3x3 conv: each thread 4 consecutive pixels per iteration ---
    float* __restrict__ dst = out + ((size_t)b * CC + c) * (HH * WW);
    #pragma unroll
    for (int it = 0; it < 4; it++) {
        const int y = ybase + it * 16;

        float a0 = 0.f, a1 = 0.f, a2 = 0.f, a3 = 0.f;
        #pragma unroll
        for (int ky = 0; ky < 3; ky++) {
            // tile row y+ky covers displaced rows (y-1+ky); cols x4..x4+5
            const float* r = &tile[(y + ky) * SM_W + x4];
            const float4 va = *(const float4*)(r);       // aligned
            const float4 vb = *(const float4*)(r + 4);   // aligned (use .x,.y)
            const float w0 = w[ky * 3 + 0];
            const float w1 = w[ky * 3 + 1];
            const float w2 = w[ky * 3 + 2];
            a0 = fmaf(w0, va.x, fmaf(w1, va.y, fmaf(w2, va.z, a0)));
            a1 = fmaf(w0, va.y, fmaf(w1, va.z, fmaf(w2, va.w, a1)));
            a2 = fmaf(w0, va.z, fmaf(w1, va.w, fmaf(w2, vb.x, a2)));
            a3 = fmaf(w0, va.w, fmaf(w1, vb.x, fmaf(w2, vb.y, a3)));
        }
        *(float4*)&dst[y * WW + x4] = make_float4(a0, a1, a2, a3);
    }
}

extern "C" void kernel_launch(void* const* d_in, const int* in_sizes, int n_in,
                              void* d_out, int out_size)
{
    const float* inp    = (const float*)d_in[0];   // (32, 384, 64, 64) fp32
    const float* offset = (const float*)d_in[1];   // (48, 2) fp32
    float* out          = (float*)d_out;           // (32, 384, 64, 64) fp32

    precompute_weights<<<1, 64>>>(offset);
    dim3 grid(CC, BB);   // one CTA per (b, c) plane
    displace_gauss_kernel<<<grid, 256>>>(inp, out);
}

// round 8
// speedup vs baseline: 1.9081x; 1.2073x over previous
#include <cuda_runtime.h>
#include <math.h>

#define HH 64
#define WW 64
#define NUM_POS 48
#define CC 384
#define BB 32
#define SM_W 68           // tile row stride (floats); cols 64..67 are zero pad

struct __align__(16) PosParam {
    float wx0, wx1, wx2;
    float wy0, wy1, wy2;
    int   ox, oy;
};

__device__ PosParam g_pp[NUM_POS];

// ---- tiny LUT kernel: separable normalized Gaussian weights per position ----
__global__ void precompute_weights(const float* __restrict__ offset)
{
    const int p = threadIdx.x;
    if (p >= NUM_POS) return;
    const float offx = offset[p * 2 + 0];
    const float offy = offset[p * 2 + 1];
    const float rx = rintf(offx);                 // == iw*16 exactly (jitter < 0.5)
    const float ry = rintf(offy);
    const float fx = offx - rx;
    const float fy = offy - ry;

    float gx[3], gy[3], sx = 0.f, sy = 0.f;
    #pragma unroll
    for (int k = 0; k < 3; k++) {
        const float dx = (float)(k - 1) + fx;
        const float dy = (float)(k - 1) + fy;
        gx[k] = expf(-2.0f * dx * dx);            // sigma = 0.5
        gy[k] = expf(-2.0f * dy * dy);
        sx += gx[k];
        sy += gy[k];
    }
    const float ix = 1.0f / sx, iy = 1.0f / sy;   // normalizer factors (separable)
    PosParam pp;
    pp.wx0 = gx[0] * ix; pp.wx1 = gx[1] * ix; pp.wx2 = gx[2] * ix;
    pp.wy0 = gy[0] * iy; pp.wy1 = gy[1] * iy; pp.wy2 = gy[2] * iy;
    pp.ox = (int)rx;     pp.oy = (int)ry;
    g_pp[p] = pp;
}

// ---- main fused kernel: displace + separable 3x3 Gaussian ----
__global__ __launch_bounds__(256, 8)
void displace_gauss_kernel(const float* __restrict__ inp,
                           float* __restrict__ out)
{
    // raw + 4-float lead pad so tile[-1] (row 0, col -1) is a valid zero.
    __shared__ float tile_raw[66 * SM_W + 4];
    float* tile = tile_raw + 4;        // tile[(y+1)*SM_W + x] = displaced(y,x)

    const int c = blockIdx.x;
    const int b = blockIdx.y;
    const int tid = threadIdx.x;

    const PosParam pp = g_pp[c >> 3];
    const int ox = pp.ox, oy = pp.oy;  // multiples of 16 by construction
    const float wx0 = pp.wx0, wx1 = pp.wx1, wx2 = pp.wx2;
    const float wy0 = pp.wy0, wy1 = pp.wy1, wy2 = pp.wy2;

    // --- zero pads: rows 0 & 65 (17 float4 each), cols 64-67 rows 1..64,
    //     plus the 4-float lead pad. 99 STS.128 total. ---
    const float4 z4 = make_float4(0.f, 0.f, 0.f, 0.f);
    if (tid < 99) {
        if (tid == 98) {
            *(float4*)tile_raw = z4;                         // lead pad
        } else {
            int r, c4;
            if (tid < 17)      { r = 0;        c4 = tid * 4;        }
            else if (tid < 34) { r = 65;       c4 = (tid - 17) * 4; }
            else               { r = tid - 33; c4 = 64;             }  // rows 1..64
            *(float4*)&tile[r * SM_W + c4] = z4;
        }
    }

    // --- interior fill: displaced (y,x) -> tile[y+1][x], aligned STS.128 ---
    const float* __restrict__ src = inp + ((size_t)b * CC + c) * (HH * WW);
    const int q     = tid & 15;
    const int x4    = q << 2;
    const int sx    = x4 - ox;                 // aligned: ox % 16 == 0
    const bool okx  = (unsigned)sx < (unsigned)WW;
    const int ybase = tid >> 4;

    #pragma unroll
    for (int k = 0; k < 4; k++) {
        const int y  = ybase + k * 16;
        const int sy = y - oy;
        float4 v = z4;
        if (okx && (unsigned)sy < (unsigned)HH)
            v = *(const float4*)(src + sy * WW + sx);
        *(float4*)&tile[(y + 1) * SM_W + x4] = v;
    }
    __syncthreads();

    // --- separable conv: 4-col x 4-row patch per thread, rolling hconv rows ---
    const int cg    = tid & 15;
    const int strip = tid >> 4;
    const int xx4 = cg << 2;
    const int y0  = strip << 2;

    // hconv of tile row T for output cols xx4..xx4+3:
    // left scalar (col -1 wraps into prev row's zero pad), aligned float4, right scalar
    #define HCONV(H, T)                                                        \
        {                                                                      \
            const float* _r = &tile[(T) * SM_W + xx4];                         \
            const float  lf = _r[-1];                                          \
            const float4 va = *(const float4*)_r;                              \
            const float  rt = _r[4];                                           \
            H.x = fmaf(wx0, lf,   fmaf(wx1, va.x, wx2 * va.y));                \
            H.y = fmaf(wx0, va.x, fmaf(wx1, va.y, wx2 * va.z));                \
            H.z = fmaf(wx0, va.y, fmaf(wx1, va.z, wx2 * va.w));                \
            H.w = fmaf(wx0, va.z, fmaf(wx1, va.w, wx2 * rt));                  \
        }

    float* __restrict__ dst = out + ((size_t)b * CC + c) * (HH * WW);

    float4 h0, h1, hn;
    HCONV(h0, y0 + 0);                 // tile row for displaced y0-1
    HCONV(h1, y0 + 1);                 // tile row for displaced y0
    #pragma unroll
    for (int r = 0; r < 4; r++) {
        HCONV(hn, y0 + 2 + r);         // tile row for displaced y0+r+1
        float4 o;
        o.x = fmaf(wy0, h0.x, fmaf(wy1, h1.x, wy2 * hn.x));
        o.y = fmaf(wy0, h0.y, fmaf(wy1, h1.y, wy2 * hn.y));
        o.z = fmaf(wy0, h0.z, fmaf(wy1, h1.z, wy2 * hn.z));
        o.w = fmaf(wy0, h0.w, fmaf(wy1, h1.w, wy2 * hn.w));
        *(float4*)&dst[(y0 + r) * WW + xx4] = o;
        h0 = h1;
        h1 = hn;
    }
    #undef HCONV
}

extern "C" void kernel_launch(void* const* d_in, const int* in_sizes, int n_in,
                              void* d_out, int out_size)
{
    const float* inp    = (const float*)d_in[0];   // (32, 384, 64, 64) fp32
    const float* offset = (const float*)d_in[1];   // (48, 2) fp32
    float* out          = (float*)d_out;           // (32, 384, 64, 64) fp32

    precompute_weights<<<1, 64>>>(offset);
    dim3 grid(CC, BB);   // one CTA per (b, c) plane
    displace_gauss_kernel<<<grid, 256>>>(inp, out);
}